// round 9
// baseline (speedup 1.0000x reference)
#include <cuda_runtime.h>
#include <cuda_bf16.h>
#include <stdint.h>
#include <cstdint>
#include <math.h>

#define B_  256
#define L_  196
#define AF  2048   // ATT_FEAT
#define AH  512    // ATT_HID
#define RS  512    // RNN_SIZE
#define IE  512    // INPUT_ENC
#define BL  (B_*L_)   // 50176

// ---------------- scratch (device globals; no allocation allowed) ----------
__device__ float g_att_h[B_*AH];          // h0@W_h2a.T + b_h2a + b_ctx
__device__ float g_scores_part[4*BL];     // per col-block partial scores
__device__ float g_weight[B_*L_];
__device__ float g_att_res[B_*AF];
__device__ float g_gates[B_*4*RS];

// ======================= helpers ==========================================
__device__ __forceinline__ uint32_t smem_u32(const void* p) {
    uint32_t a;
    asm("{ .reg .u64 t; cvta.to.shared.u64 t, %1; cvt.u32.u64 %0, t; }"
        : "=r"(a) : "l"(p));
    return a;
}

// fp32x4 -> hi/lo bf16x2 pairs
__device__ __forceinline__ void split4(float4 v, uint2& hw, uint2& lw) {
    __nv_bfloat16 h0 = __float2bfloat16_rn(v.x);
    __nv_bfloat16 h1 = __float2bfloat16_rn(v.y);
    __nv_bfloat16 h2 = __float2bfloat16_rn(v.z);
    __nv_bfloat16 h3 = __float2bfloat16_rn(v.w);
    __nv_bfloat16 l0 = __float2bfloat16_rn(v.x - __bfloat162float(h0));
    __nv_bfloat16 l1 = __float2bfloat16_rn(v.y - __bfloat162float(h1));
    __nv_bfloat16 l2 = __float2bfloat16_rn(v.z - __bfloat162float(h2));
    __nv_bfloat16 l3 = __float2bfloat16_rn(v.w - __bfloat162float(h3));
    hw.x = ((uint32_t)__bfloat16_as_ushort(h1) << 16) | __bfloat16_as_ushort(h0);
    hw.y = ((uint32_t)__bfloat16_as_ushort(h3) << 16) | __bfloat16_as_ushort(h2);
    lw.x = ((uint32_t)__bfloat16_as_ushort(l1) << 16) | __bfloat16_as_ushort(l0);
    lw.y = ((uint32_t)__bfloat16_as_ushort(l3) << 16) | __bfloat16_as_ushort(l2);
}

#define LDMX4(r0, r1, r2, r3, addr)                                          \
    asm volatile("ldmatrix.sync.aligned.m8n8.x4.shared.b16 {%0,%1,%2,%3}, [%4];" \
                 : "=r"(r0), "=r"(r1), "=r"(r2), "=r"(r3) : "r"(addr))

#define MMA16816(c, a, b0, b1)                                               \
    asm volatile("mma.sync.aligned.m16n8k16.row.col.f32.bf16.bf16.f32 "      \
                 "{%0,%1,%2,%3}, {%4,%5,%6,%7}, {%8,%9}, {%0,%1,%2,%3};"     \
                 : "+f"((c)[0]), "+f"((c)[1]), "+f"((c)[2]), "+f"((c)[3])    \
                 : "r"((a)[0]), "r"((a)[1]), "r"((a)[2]), "r"((a)[3]),       \
                   "r"(b0), "r"(b1))

// ================= split-bf16 mma.sync fused score GEMM ====================
#define TM 128
#define TN 128
#define TKF 32                 // fp32 K per stage
#define PITCHB 80              // bytes per smem row (32 bf16 + 8 pad)
#define ARR 10240              // 128 * 80
#define STGB (4*ARR)           // Ah, Al, Bh, Bl = 40960
#define NST (AF / TKF)         // 64 stages

__global__ void __launch_bounds__(256, 1)
att_score_mma(const float* __restrict__ A,      // [BL, AF]
              const float* __restrict__ Wc,     // [AH, AF]
              const float* __restrict__ W_alpha)
{
    extern __shared__ char dsm[];
    __shared__ float red[TM][2];
    const int tid  = threadIdx.x;
    const int lane = tid & 31, wid = tid >> 5;
    const int warp_m = wid & 3, warp_n = wid >> 2;
    const int row0 = blockIdx.y * TM;
    const int n0   = blockIdx.x * TN;
    const uint32_t sb = smem_u32(dsm);

    // per-thread LDG targets (fixed across stages): 4 float4 of A, 4 of B
    const int lr = tid >> 3;            // 0..31 base row group (row = lr + 32*i)
    const int lc = (tid & 7) * 4;       // fp32 col within K-chunk
    const float* Aptr = &A[(size_t)(row0 + lr) * AF + lc];
    const float* Bptr = &Wc[(size_t)(n0 + lr) * AF + lc];

    float cfr[2][8][4];
    #pragma unroll
    for (int mt = 0; mt < 2; mt++)
        #pragma unroll
        for (int nt = 0; nt < 8; nt++)
            #pragma unroll
            for (int j = 0; j < 4; j++) cfr[mt][nt][j] = 0.f;

    const uint32_t lrow = lane & 15;
    const uint32_t loff = (uint32_t)((lane >> 4) & 1) * 16;  // 0 / 16 bytes

    float4 pa[4], pb[4];

    // ---- preload stage 0 ----
    #pragma unroll
    for (int i = 0; i < 4; i++) {
        pa[i] = *(const float4*)(Aptr + (size_t)(i * 32) * AF);
        pb[i] = *(const float4*)(Bptr + (size_t)(i * 32) * AF);
    }
    {
        char* SB = dsm;
        #pragma unroll
        for (int i = 0; i < 4; i++) {
            int off = (lr + i * 32) * PITCHB + lc * 2;
            uint2 hw, lw; split4(pa[i], hw, lw);
            *(uint2*)(SB + off) = hw;  *(uint2*)(SB + ARR + off) = lw;
            split4(pb[i], hw, lw);
            *(uint2*)(SB + 2 * ARR + off) = hw;  *(uint2*)(SB + 3 * ARR + off) = lw;
        }
    }
    __syncthreads();

    for (int ks = 0; ks < NST; ks++) {
        const int s = ks & 1;

        // ---- issue next-stage global loads (hidden behind MMA section) ----
        if (ks + 1 < NST) {
            const float* ap = Aptr + (ks + 1) * TKF;
            const float* bp = Bptr + (ks + 1) * TKF;
            #pragma unroll
            for (int i = 0; i < 4; i++) {
                pa[i] = *(const float4*)(ap + (size_t)(i * 32) * AF);
                pb[i] = *(const float4*)(bp + (size_t)(i * 32) * AF);
            }
        }

        // ---- MMA on current stage with fragment reuse ----
        const uint32_t base = sb + s * STGB;
        #pragma unroll
        for (int kk = 0; kk < 2; kk++) {
            const uint32_t acol = (uint32_t)kk * 32 + loff;
            uint32_t afh[2][4], afl[2][4], bfr[4][4];
            #pragma unroll
            for (int mt = 0; mt < 2; mt++) {
                uint32_t r = (uint32_t)(warp_m * 32 + mt * 16 + lrow) * PITCHB + acol;
                LDMX4(afh[mt][0], afh[mt][1], afh[mt][2], afh[mt][3], base + r);
                LDMX4(afl[mt][0], afl[mt][1], afl[mt][2], afl[mt][3], base + ARR + r);
            }
            #pragma unroll
            for (int ng = 0; ng < 4; ng++) {
                uint32_t r = (uint32_t)(warp_n * 64 + ng * 16 + lrow) * PITCHB + acol;
                LDMX4(bfr[ng][0], bfr[ng][1], bfr[ng][2], bfr[ng][3], base + 2 * ARR + r);
            }
            // hh + lh share B_hi fragments
            #pragma unroll
            for (int mt = 0; mt < 2; mt++)
                #pragma unroll
                for (int nt = 0; nt < 8; nt++) {
                    int ng = nt >> 1, od = nt & 1;
                    MMA16816(cfr[mt][nt], afh[mt], bfr[ng][od ? 1 : 0], bfr[ng][od ? 3 : 2]);
                    MMA16816(cfr[mt][nt], afl[mt], bfr[ng][od ? 1 : 0], bfr[ng][od ? 3 : 2]);
                }
            // hl: reload B_lo fragments, reuse A_hi
            #pragma unroll
            for (int ng = 0; ng < 4; ng++) {
                uint32_t r = (uint32_t)(warp_n * 64 + ng * 16 + lrow) * PITCHB + acol;
                LDMX4(bfr[ng][0], bfr[ng][1], bfr[ng][2], bfr[ng][3], base + 3 * ARR + r);
            }
            #pragma unroll
            for (int mt = 0; mt < 2; mt++)
                #pragma unroll
                for (int nt = 0; nt < 8; nt++) {
                    int ng = nt >> 1, od = nt & 1;
                    MMA16816(cfr[mt][nt], afh[mt], bfr[ng][od ? 1 : 0], bfr[ng][od ? 3 : 2]);
                }
        }

        // ---- convert + store next stage ----
        if (ks + 1 < NST) {
            char* SB = dsm + ((ks + 1) & 1) * STGB;
            #pragma unroll
            for (int i = 0; i < 4; i++) {
                int off = (lr + i * 32) * PITCHB + lc * 2;
                uint2 hw, lw; split4(pa[i], hw, lw);
                *(uint2*)(SB + off) = hw;  *(uint2*)(SB + ARR + off) = lw;
                split4(pb[i], hw, lw);
                *(uint2*)(SB + 2 * ARR + off) = hw;  *(uint2*)(SB + 3 * ARR + off) = lw;
            }
        }
        __syncthreads();
    }

    // ---- epilogue: tanh + dot W_alpha, reduce to per-row partials ----
    const int g = lane >> 2, tg = lane & 3;
    #pragma unroll
    for (int mt = 0; mt < 2; mt++) {
        int lr0 = warp_m * 32 + mt * 16 + g;
        int grow0 = row0 + lr0;
        int bb0 = grow0 / L_;
        int bb1 = (grow0 + 8) / L_;
        const float* ah0 = &g_att_h[bb0 * AH + n0];
        const float* ah1 = &g_att_h[bb1 * AH + n0];
        float p0 = 0.f, p1 = 0.f;
        #pragma unroll
        for (int nt = 0; nt < 8; nt++) {
            int col = warp_n * 64 + nt * 8 + tg * 2;
            float wa0 = __ldg(&W_alpha[n0 + col]);
            float wa1 = __ldg(&W_alpha[n0 + col + 1]);
            p0 += wa0 * tanhf(cfr[mt][nt][0] + __ldg(&ah0[col]))
                + wa1 * tanhf(cfr[mt][nt][1] + __ldg(&ah0[col + 1]));
            p1 += wa0 * tanhf(cfr[mt][nt][2] + __ldg(&ah1[col]))
                + wa1 * tanhf(cfr[mt][nt][3] + __ldg(&ah1[col + 1]));
        }
        p0 += __shfl_xor_sync(0xFFFFFFFFu, p0, 1);
        p0 += __shfl_xor_sync(0xFFFFFFFFu, p0, 2);
        p1 += __shfl_xor_sync(0xFFFFFFFFu, p1, 1);
        p1 += __shfl_xor_sync(0xFFFFFFFFu, p1, 2);
        if (tg == 0) {
            red[lr0][warp_n]     = p0;
            red[lr0 + 8][warp_n] = p1;
        }
    }
    __syncthreads();
    if (tid < TM)
        g_scores_part[(size_t)blockIdx.x * BL + row0 + tid] = red[tid][0] + red[tid][1];
}

// ---------------- small GEMM: att_h = h0 @ W_h2a.T + b_h2a + b_ctx ---------
__global__ __launch_bounds__(256)
void att_h_kernel(const float* __restrict__ h0,
                  const float* __restrict__ W_h2a,
                  const float* __restrict__ b_h2a,
                  const float* __restrict__ b_ctx)
{
    const int BM = 64, BN = 64, BK = 16;
    __shared__ float As[BK][BM + 4];
    __shared__ float Bs[BK][BN + 4];
    int tid = threadIdx.x;
    int tx = tid & 15, ty = tid >> 4;
    int row0 = blockIdx.y * BM;
    int col0 = blockIdx.x * BN;
    float acc[4][4] = {};

    for (int k0 = 0; k0 < RS; k0 += BK) {
        int m  = tid >> 2;
        int kk = (tid & 3) * 4;
        float4 va = *(const float4*)&h0[(row0 + m) * RS + k0 + kk];
        As[kk + 0][m] = va.x; As[kk + 1][m] = va.y;
        As[kk + 2][m] = va.z; As[kk + 3][m] = va.w;
        float4 vb = *(const float4*)&W_h2a[(col0 + m) * RS + k0 + kk];
        Bs[kk + 0][m] = vb.x; Bs[kk + 1][m] = vb.y;
        Bs[kk + 2][m] = vb.z; Bs[kk + 3][m] = vb.w;
        __syncthreads();
        #pragma unroll
        for (int k = 0; k < BK; k++) {
            float a[4], b[4];
            *(float4*)a = *(const float4*)&As[k][ty * 4];
            *(float4*)b = *(const float4*)&Bs[k][tx * 4];
            #pragma unroll
            for (int i = 0; i < 4; i++)
                #pragma unroll
                for (int j = 0; j < 4; j++)
                    acc[i][j] = fmaf(a[i], b[j], acc[i][j]);
        }
        __syncthreads();
    }
    #pragma unroll
    for (int i = 0; i < 4; i++) {
        int r = row0 + ty * 4 + i;
        #pragma unroll
        for (int j = 0; j < 4; j++) {
            int c = col0 + tx * 4 + j;
            g_att_h[r * AH + c] = acc[i][j] + b_h2a[c] + b_ctx[c];
        }
    }
}

// ---------------- softmax over L per batch --------------------------------
__global__ void softmax_kernel(const float* __restrict__ b_alpha)
{
    int b = blockIdx.x;
    int t = threadIdx.x;   // 256
    __shared__ float sm[256];
    float v = 0.f;
    float s = -1e30f;
    if (t < L_) {
        int idx = b * L_ + t;
        v = g_scores_part[idx] + g_scores_part[BL + idx] +
            g_scores_part[2 * BL + idx] + g_scores_part[3 * BL + idx] +
            b_alpha[0];
        s = v;
    }
    sm[t] = s; __syncthreads();
    for (int o = 128; o > 0; o >>= 1) {
        if (t < o) sm[t] = fmaxf(sm[t], sm[t + o]);
        __syncthreads();
    }
    float mx = sm[0];
    __syncthreads();
    float e = (t < L_) ? expf(v - mx) : 0.f;
    sm[t] = e; __syncthreads();
    for (int o = 128; o > 0; o >>= 1) {
        if (t < o) sm[t] += sm[t + o];
        __syncthreads();
    }
    float inv = 1.f / sm[0];
    if (t < L_) g_weight[b * L_ + t] = e * inv;
}

// ---------------- att_res = weight @ att_feats (memory-bound) -------------
__global__ __launch_bounds__(256)
void att_res_kernel(const float* __restrict__ att_feats)
{
    int b = blockIdx.x;
    int t = threadIdx.x;  // 256
    __shared__ float ws[L_];
    if (t < L_) ws[t] = g_weight[b * L_ + t];
    __syncthreads();
    const float* base = att_feats + (size_t)b * L_ * AF;
    int c0 = t * 4, c1 = 1024 + t * 4;
    float4 a0 = {0,0,0,0}, a1 = {0,0,0,0};
    for (int l = 0; l < L_; l++) {
        float w = ws[l];
        float4 v0 = *(const float4*)&base[(size_t)l * AF + c0];
        float4 v1 = *(const float4*)&base[(size_t)l * AF + c1];
        a0.x = fmaf(w, v0.x, a0.x); a0.y = fmaf(w, v0.y, a0.y);
        a0.z = fmaf(w, v0.z, a0.z); a0.w = fmaf(w, v0.w, a0.w);
        a1.x = fmaf(w, v1.x, a1.x); a1.y = fmaf(w, v1.y, a1.y);
        a1.z = fmaf(w, v1.z, a1.z); a1.w = fmaf(w, v1.w, a1.w);
    }
    *(float4*)&g_att_res[b * AF + c0] = a0;
    *(float4*)&g_att_res[b * AF + c1] = a1;
}

// ---------------- gates GEMM: [xt|att_res|h0] @ [W_ih|W_hh].T -------------
__device__ __forceinline__ float4 load_Ag(const float* xt, const float* h0,
                                          int row, int k)
{
    if (k < IE)           return *(const float4*)&xt[row * IE + k];
    else if (k < IE + AF) return *(const float4*)&g_att_res[row * AF + (k - IE)];
    else                  return *(const float4*)&h0[row * RS + (k - IE - AF)];
}
__device__ __forceinline__ float4 load_Bg(const float* W_ih, const float* W_hh,
                                          int col, int k)
{
    if (k < IE + AF) return *(const float4*)&W_ih[(size_t)col * (IE + AF) + k];
    else             return *(const float4*)&W_hh[col * RS + (k - IE - AF)];
}

__global__ __launch_bounds__(256)
void gates_kernel(const float* __restrict__ xt,
                  const float* __restrict__ h0,
                  const float* __restrict__ W_ih,
                  const float* __restrict__ W_hh)
{
    const int BM = 128, BN = 128, BK = 16, KK = IE + AF + RS; // 3072
    __shared__ float As[BK][BM + 4];
    __shared__ float Bs[BK][BN + 4];
    int tid = threadIdx.x;
    int tx = tid & 15, ty = tid >> 4;
    int row0 = blockIdx.y * BM;
    int col0 = blockIdx.x * BN;
    float acc[8][8] = {};

    for (int k0 = 0; k0 < KK; k0 += BK) {
        #pragma unroll
        for (int i = 0; i < 2; i++) {
            int e  = tid + i * 256;
            int m  = e >> 2;
            int kk = (e & 3) * 4;
            float4 va = load_Ag(xt, h0, row0 + m, k0 + kk);
            As[kk + 0][m] = va.x; As[kk + 1][m] = va.y;
            As[kk + 2][m] = va.z; As[kk + 3][m] = va.w;
            float4 vb = load_Bg(W_ih, W_hh, col0 + m, k0 + kk);
            Bs[kk + 0][m] = vb.x; Bs[kk + 1][m] = vb.y;
            Bs[kk + 2][m] = vb.z; Bs[kk + 3][m] = vb.w;
        }
        __syncthreads();
        #pragma unroll
        for (int k = 0; k < BK; k++) {
            float a[8], b[8];
            *(float4*)&a[0] = *(const float4*)&As[k][ty * 8];
            *(float4*)&a[4] = *(const float4*)&As[k][ty * 8 + 4];
            *(float4*)&b[0] = *(const float4*)&Bs[k][tx * 8];
            *(float4*)&b[4] = *(const float4*)&Bs[k][tx * 8 + 4];
            #pragma unroll
            for (int i = 0; i < 8; i++)
                #pragma unroll
                for (int j = 0; j < 8; j++)
                    acc[i][j] = fmaf(a[i], b[j], acc[i][j]);
        }
        __syncthreads();
    }
    #pragma unroll
    for (int i = 0; i < 8; i++) {
        int r = row0 + ty * 8 + i;
        #pragma unroll
        for (int j = 0; j < 8; j++) {
            int c = col0 + tx * 8 + j;
            g_gates[r * (4 * RS) + c] = acc[i][j];
        }
    }
}

// ---------------- LSTM pointwise + output writes --------------------------
__global__ void lstm_kernel(const float* __restrict__ c0,
                            float* __restrict__ out, int out_size)
{
    int idx = blockIdx.x * 256 + threadIdx.x;
    if (idx >= B_ * RS) return;
    int b = idx / RS, j = idx % RS;
    const float* g = &g_gates[b * 4 * RS];
    float i_ = 1.f / (1.f + expf(-g[j]));
    float f_ = 1.f / (1.f + expf(-g[RS + j]));
    float gg = tanhf(g[2 * RS + j]);
    float o_ = 1.f / (1.f + expf(-g[3 * RS + j]));
    float c  = f_ * c0[idx] + i_ * gg;
    float h  = o_ * tanhf(c);
    out[idx] = h;
    if (out_size >= 3 * B_ * RS) {
        out[B_ * RS + idx]     = h;   // h_new[None]
        out[2 * B_ * RS + idx] = c;   // c_new[None]
    }
}

// ---------------- launch ---------------------------------------------------
extern "C" void kernel_launch(void* const* d_in, const int* in_sizes, int n_in,
                              void* d_out, int out_size)
{
    const float* xt        = (const float*)d_in[0];
    // d_in[1] = fc_feats (unused by reference)
    const float* att_feats = (const float*)d_in[2];
    const float* h0        = (const float*)d_in[3];
    const float* c0        = (const float*)d_in[4];
    const float* W_ctx     = (const float*)d_in[5];
    const float* b_ctx     = (const float*)d_in[6];
    const float* W_h2a     = (const float*)d_in[7];
    const float* b_h2a     = (const float*)d_in[8];
    const float* W_alpha   = (const float*)d_in[9];
    const float* b_alpha   = (const float*)d_in[10];
    const float* W_ih      = (const float*)d_in[11];
    const float* W_hh      = (const float*)d_in[12];
    float* out = (float*)d_out;

    cudaFuncSetAttribute(att_score_mma,
                         cudaFuncAttributeMaxDynamicSharedMemorySize,
                         2 * STGB);

    att_h_kernel<<<dim3(AH / 64, B_ / 64), 256>>>(h0, W_h2a, b_h2a, b_ctx);
    att_score_mma<<<dim3(AH / TN, BL / TM), 256, 2 * STGB>>>(att_feats, W_ctx, W_alpha);
    softmax_kernel<<<B_, 256>>>(b_alpha);
    att_res_kernel<<<B_, 256>>>(att_feats);
    gates_kernel<<<dim3(4 * RS / 128, B_ / 128), 256>>>(xt, h0, W_ih, W_hh);
    lstm_kernel<<<(B_ * RS + 255) / 256, 256>>>(c0, out, out_size);
}

// round 12
// speedup vs baseline: 1.2405x; 1.2405x over previous
#include <cuda_runtime.h>
#include <cuda_fp16.h>
#include <stdint.h>
#include <cstdint>
#include <math.h>

#define B_  256
#define L_  196
#define AF  2048   // ATT_FEAT
#define AH  512    // ATT_HID
#define RS  512    // RNN_SIZE
#define IE  512    // INPUT_ENC
#define BL  (B_*L_)   // 50176

// ---------------- scratch (device globals; no allocation allowed) ----------
__device__ float g_att_h[B_*AH];          // h0@W_h2a.T + b_h2a + b_ctx
__device__ float g_scores_part[4*BL];     // per col-block partial scores
__device__ float g_weight[B_*L_];
__device__ float g_att_res[B_*AF];
__device__ float g_gates[B_*4*RS];

// ======================= helpers ==========================================
__device__ __forceinline__ uint32_t smem_u32(const void* p) {
    uint32_t a;
    asm("{ .reg .u64 t; cvta.to.shared.u64 t, %1; cvt.u32.u64 %0, t; }"
        : "=r"(a) : "l"(p));
    return a;
}

// fp32x4 -> fp16x4 (packed in uint2)
__device__ __forceinline__ uint2 cvt4(float4 v) {
    __half2 a = __floats2half2_rn(v.x, v.y);
    __half2 b = __floats2half2_rn(v.z, v.w);
    uint2 r;
    r.x = *(uint32_t*)&a;
    r.y = *(uint32_t*)&b;
    return r;
}

#define LDMX4(r0, r1, r2, r3, addr)                                          \
    asm volatile("ldmatrix.sync.aligned.m8n8.x4.shared.b16 {%0,%1,%2,%3}, [%4];" \
                 : "=r"(r0), "=r"(r1), "=r"(r2), "=r"(r3) : "r"(addr))

#define MMA16816(c, a, b0, b1)                                               \
    asm volatile("mma.sync.aligned.m16n8k16.row.col.f32.f16.f16.f32 "        \
                 "{%0,%1,%2,%3}, {%4,%5,%6,%7}, {%8,%9}, {%0,%1,%2,%3};"     \
                 : "+f"((c)[0]), "+f"((c)[1]), "+f"((c)[2]), "+f"((c)[3])    \
                 : "r"((a)[0]), "r"((a)[1]), "r"((a)[2]), "r"((a)[3]),       \
                   "r"(b0), "r"(b1))

// ================= single-pass fp16 mma.sync fused score GEMM ==============
// D[m,h] = sum_k A[m,k]*Wc[h,k], then partial score
//   p[m] = sum_{h in 128-col block} W_alpha[h]*tanh(D[m,h] + att_h[b,h])
#define TM 128
#define TN 128
#define TKF 32                 // fp32 K per stage
#define PITCHB 80              // bytes per smem row (32 fp16 + 16 pad)
#define ARR 10240              // 128 * 80
#define STGB (2*ARR)           // Ah, Bh = 20480
#define NST (AF / TKF)         // 64 stages

__global__ void __launch_bounds__(256, 2)
att_score_mma(const float* __restrict__ A,      // [BL, AF]
              const float* __restrict__ Wc,     // [AH, AF]
              const float* __restrict__ W_alpha)
{
    extern __shared__ char dsm[];
    __shared__ float red[TM][2];
    const int tid  = threadIdx.x;
    const int lane = tid & 31, wid = tid >> 5;
    const int warp_m = wid & 3, warp_n = wid >> 2;
    const int row0 = blockIdx.y * TM;
    const int n0   = blockIdx.x * TN;
    const uint32_t sb = smem_u32(dsm);

    float cfr[2][8][4];
    #pragma unroll
    for (int mt = 0; mt < 2; mt++)
        #pragma unroll
        for (int nt = 0; nt < 8; nt++)
            #pragma unroll
            for (int j = 0; j < 4; j++) cfr[mt][nt][j] = 0.f;

    const uint32_t lrow = lane & 15;
    const uint32_t loff = (uint32_t)((lane >> 4) & 1) * 16;  // 0 / 16 bytes

    for (int ks = 0; ks < NST; ks++) {
        const int s = ks & 1;
        char* SB = dsm + s * STGB;
        const int k0 = ks * TKF;

        // ---- load + convert A (128x32) and B (128x32) fp32 tiles ----
        #pragma unroll
        for (int i = 0; i < 4; i++) {
            int e = tid + i * 256;
            int r = e >> 3, c = (e & 7) * 4;
            float4 v = *(const float4*)&A[(size_t)(row0 + r) * AF + k0 + c];
            *(uint2*)(SB + r * PITCHB + c * 2) = cvt4(v);
        }
        #pragma unroll
        for (int i = 0; i < 4; i++) {
            int e = tid + i * 256;
            int r = e >> 3, c = (e & 7) * 4;
            float4 v = *(const float4*)&Wc[(size_t)(n0 + r) * AF + k0 + c];
            *(uint2*)(SB + ARR + r * PITCHB + c * 2) = cvt4(v);
        }
        __syncthreads();

        // ---- MMA on current stage ----
        const uint32_t base = sb + s * STGB;
        #pragma unroll
        for (int kk = 0; kk < 2; kk++) {
            const uint32_t acol = (uint32_t)kk * 32 + loff;
            uint32_t af[2][4], bf[4][4];
            #pragma unroll
            for (int mt = 0; mt < 2; mt++) {
                uint32_t r = (uint32_t)(warp_m * 32 + mt * 16 + lrow) * PITCHB + acol;
                LDMX4(af[mt][0], af[mt][1], af[mt][2], af[mt][3], base + r);
            }
            #pragma unroll
            for (int ng = 0; ng < 4; ng++) {
                uint32_t r = (uint32_t)(warp_n * 64 + ng * 16 + lrow) * PITCHB + acol;
                LDMX4(bf[ng][0], bf[ng][1], bf[ng][2], bf[ng][3], base + ARR + r);
            }
            #pragma unroll
            for (int mt = 0; mt < 2; mt++)
                #pragma unroll
                for (int nt = 0; nt < 8; nt++) {
                    int ng = nt >> 1, od = nt & 1;
                    MMA16816(cfr[mt][nt], af[mt],
                             bf[ng][od ? 1 : 0], bf[ng][od ? 3 : 2]);
                }
        }
        __syncthreads();
    }

    // ---- epilogue: tanh + dot W_alpha, reduce to per-row partials ----
    const int g = lane >> 2, tg = lane & 3;
    #pragma unroll
    for (int mt = 0; mt < 2; mt++) {
        int lr0 = warp_m * 32 + mt * 16 + g;
        int grow0 = row0 + lr0;
        int bb0 = grow0 / L_;
        int bb1 = (grow0 + 8) / L_;
        const float* ah0 = &g_att_h[bb0 * AH + n0];
        const float* ah1 = &g_att_h[bb1 * AH + n0];
        float p0 = 0.f, p1 = 0.f;
        #pragma unroll
        for (int nt = 0; nt < 8; nt++) {
            int col = warp_n * 64 + nt * 8 + tg * 2;
            float wa0 = __ldg(&W_alpha[n0 + col]);
            float wa1 = __ldg(&W_alpha[n0 + col + 1]);
            p0 += wa0 * tanhf(cfr[mt][nt][0] + __ldg(&ah0[col]))
                + wa1 * tanhf(cfr[mt][nt][1] + __ldg(&ah0[col + 1]));
            p1 += wa0 * tanhf(cfr[mt][nt][2] + __ldg(&ah1[col]))
                + wa1 * tanhf(cfr[mt][nt][3] + __ldg(&ah1[col + 1]));
        }
        p0 += __shfl_xor_sync(0xFFFFFFFFu, p0, 1);
        p0 += __shfl_xor_sync(0xFFFFFFFFu, p0, 2);
        p1 += __shfl_xor_sync(0xFFFFFFFFu, p1, 1);
        p1 += __shfl_xor_sync(0xFFFFFFFFu, p1, 2);
        if (tg == 0) {
            red[lr0][warp_n]     = p0;
            red[lr0 + 8][warp_n] = p1;
        }
    }
    __syncthreads();
    if (tid < TM)
        g_scores_part[(size_t)blockIdx.x * BL + row0 + tid] = red[tid][0] + red[tid][1];
}

// ---------------- small GEMM: att_h = h0 @ W_h2a.T + b_h2a + b_ctx ---------
__global__ __launch_bounds__(256)
void att_h_kernel(const float* __restrict__ h0,
                  const float* __restrict__ W_h2a,
                  const float* __restrict__ b_h2a,
                  const float* __restrict__ b_ctx)
{
    const int BM = 64, BN = 64, BK = 16;
    __shared__ float As[BK][BM + 4];
    __shared__ float Bs[BK][BN + 4];
    int tid = threadIdx.x;
    int tx = tid & 15, ty = tid >> 4;
    int row0 = blockIdx.y * BM;
    int col0 = blockIdx.x * BN;
    float acc[4][4] = {};

    for (int k0 = 0; k0 < RS; k0 += BK) {
        int m  = tid >> 2;
        int kk = (tid & 3) * 4;
        float4 va = *(const float4*)&h0[(row0 + m) * RS + k0 + kk];
        As[kk + 0][m] = va.x; As[kk + 1][m] = va.y;
        As[kk + 2][m] = va.z; As[kk + 3][m] = va.w;
        float4 vb = *(const float4*)&W_h2a[(col0 + m) * RS + k0 + kk];
        Bs[kk + 0][m] = vb.x; Bs[kk + 1][m] = vb.y;
        Bs[kk + 2][m] = vb.z; Bs[kk + 3][m] = vb.w;
        __syncthreads();
        #pragma unroll
        for (int k = 0; k < BK; k++) {
            float a[4], b[4];
            *(float4*)a = *(const float4*)&As[k][ty * 4];
            *(float4*)b = *(const float4*)&Bs[k][tx * 4];
            #pragma unroll
            for (int i = 0; i < 4; i++)
                #pragma unroll
                for (int j = 0; j < 4; j++)
                    acc[i][j] = fmaf(a[i], b[j], acc[i][j]);
        }
        __syncthreads();
    }
    #pragma unroll
    for (int i = 0; i < 4; i++) {
        int r = row0 + ty * 4 + i;
        #pragma unroll
        for (int j = 0; j < 4; j++) {
            int c = col0 + tx * 4 + j;
            g_att_h[r * AH + c] = acc[i][j] + b_h2a[c] + b_ctx[c];
        }
    }
}

// ---------------- softmax over L per batch --------------------------------
__global__ void softmax_kernel(const float* __restrict__ b_alpha)
{
    int b = blockIdx.x;
    int t = threadIdx.x;   // 256
    __shared__ float sm[256];
    float v = 0.f;
    float s = -1e30f;
    if (t < L_) {
        int idx = b * L_ + t;
        v = g_scores_part[idx] + g_scores_part[BL + idx] +
            g_scores_part[2 * BL + idx] + g_scores_part[3 * BL + idx] +
            b_alpha[0];
        s = v;
    }
    sm[t] = s; __syncthreads();
    for (int o = 128; o > 0; o >>= 1) {
        if (t < o) sm[t] = fmaxf(sm[t], sm[t + o]);
        __syncthreads();
    }
    float mx = sm[0];
    __syncthreads();
    float e = (t < L_) ? expf(v - mx) : 0.f;
    sm[t] = e; __syncthreads();
    for (int o = 128; o > 0; o >>= 1) {
        if (t < o) sm[t] += sm[t + o];
        __syncthreads();
    }
    float inv = 1.f / sm[0];
    if (t < L_) g_weight[b * L_ + t] = e * inv;
}

// ---------------- att_res = weight @ att_feats (memory-bound) -------------
__global__ __launch_bounds__(256)
void att_res_kernel(const float* __restrict__ att_feats)
{
    int b = blockIdx.x;
    int t = threadIdx.x;  // 256
    __shared__ float ws[L_];
    if (t < L_) ws[t] = g_weight[b * L_ + t];
    __syncthreads();
    const float* base = att_feats + (size_t)b * L_ * AF;
    int c0 = t * 4, c1 = 1024 + t * 4;
    float4 a0 = {0,0,0,0}, a1 = {0,0,0,0};
    for (int l = 0; l < L_; l++) {
        float w = ws[l];
        float4 v0 = *(const float4*)&base[(size_t)l * AF + c0];
        float4 v1 = *(const float4*)&base[(size_t)l * AF + c1];
        a0.x = fmaf(w, v0.x, a0.x); a0.y = fmaf(w, v0.y, a0.y);
        a0.z = fmaf(w, v0.z, a0.z); a0.w = fmaf(w, v0.w, a0.w);
        a1.x = fmaf(w, v1.x, a1.x); a1.y = fmaf(w, v1.y, a1.y);
        a1.z = fmaf(w, v1.z, a1.z); a1.w = fmaf(w, v1.w, a1.w);
    }
    *(float4*)&g_att_res[b * AF + c0] = a0;
    *(float4*)&g_att_res[b * AF + c1] = a1;
}

// ---------------- gates GEMM: [xt|att_res|h0] @ [W_ih|W_hh].T -------------
__device__ __forceinline__ float4 load_Ag(const float* xt, const float* h0,
                                          int row, int k)
{
    if (k < IE)           return *(const float4*)&xt[row * IE + k];
    else if (k < IE + AF) return *(const float4*)&g_att_res[row * AF + (k - IE)];
    else                  return *(const float4*)&h0[row * RS + (k - IE - AF)];
}
__device__ __forceinline__ float4 load_Bg(const float* W_ih, const float* W_hh,
                                          int col, int k)
{
    if (k < IE + AF) return *(const float4*)&W_ih[(size_t)col * (IE + AF) + k];
    else             return *(const float4*)&W_hh[col * RS + (k - IE - AF)];
}

__global__ __launch_bounds__(256)
void gates_kernel(const float* __restrict__ xt,
                  const float* __restrict__ h0,
                  const float* __restrict__ W_ih,
                  const float* __restrict__ W_hh)
{
    const int BM = 128, BN = 128, BK = 16, KK = IE + AF + RS; // 3072
    __shared__ float As[BK][BM + 4];
    __shared__ float Bs[BK][BN + 4];
    int tid = threadIdx.x;
    int tx = tid & 15, ty = tid >> 4;
    int row0 = blockIdx.y * BM;
    int col0 = blockIdx.x * BN;
    float acc[8][8] = {};

    for (int k0 = 0; k0 < KK; k0 += BK) {
        #pragma unroll
        for (int i = 0; i < 2; i++) {
            int e  = tid + i * 256;
            int m  = e >> 2;
            int kk = (e & 3) * 4;
            float4 va = load_Ag(xt, h0, row0 + m, k0 + kk);
            As[kk + 0][m] = va.x; As[kk + 1][m] = va.y;
            As[kk + 2][m] = va.z; As[kk + 3][m] = va.w;
            float4 vb = load_Bg(W_ih, W_hh, col0 + m, k0 + kk);
            Bs[kk + 0][m] = vb.x; Bs[kk + 1][m] = vb.y;
            Bs[kk + 2][m] = vb.z; Bs[kk + 3][m] = vb.w;
        }
        __syncthreads();
        #pragma unroll
        for (int k = 0; k < BK; k++) {
            float a[8], b[8];
            *(float4*)&a[0] = *(const float4*)&As[k][ty * 8];
            *(float4*)&a[4] = *(const float4*)&As[k][ty * 8 + 4];
            *(float4*)&b[0] = *(const float4*)&Bs[k][tx * 8];
            *(float4*)&b[4] = *(const float4*)&Bs[k][tx * 8 + 4];
            #pragma unroll
            for (int i = 0; i < 8; i++)
                #pragma unroll
                for (int j = 0; j < 8; j++)
                    acc[i][j] = fmaf(a[i], b[j], acc[i][j]);
        }
        __syncthreads();
    }
    #pragma unroll
    for (int i = 0; i < 8; i++) {
        int r = row0 + ty * 8 + i;
        #pragma unroll
        for (int j = 0; j < 8; j++) {
            int c = col0 + tx * 8 + j;
            g_gates[r * (4 * RS) + c] = acc[i][j];
        }
    }
}

// ---------------- LSTM pointwise + output writes --------------------------
__global__ void lstm_kernel(const float* __restrict__ c0,
                            float* __restrict__ out, int out_size)
{
    int idx = blockIdx.x * 256 + threadIdx.x;
    if (idx >= B_ * RS) return;
    int b = idx / RS, j = idx % RS;
    const float* g = &g_gates[b * 4 * RS];
    float i_ = 1.f / (1.f + expf(-g[j]));
    float f_ = 1.f / (1.f + expf(-g[RS + j]));
    float gg = tanhf(g[2 * RS + j]);
    float o_ = 1.f / (1.f + expf(-g[3 * RS + j]));
    float c  = f_ * c0[idx] + i_ * gg;
    float h  = o_ * tanhf(c);
    out[idx] = h;
    if (out_size >= 3 * B_ * RS) {
        out[B_ * RS + idx]     = h;   // h_new[None]
        out[2 * B_ * RS + idx] = c;   // c_new[None]
    }
}

// ---------------- launch ---------------------------------------------------
extern "C" void kernel_launch(void* const* d_in, const int* in_sizes, int n_in,
                              void* d_out, int out_size)
{
    const float* xt        = (const float*)d_in[0];
    // d_in[1] = fc_feats (unused by reference)
    const float* att_feats = (const float*)d_in[2];
    const float* h0        = (const float*)d_in[3];
    const float* c0        = (const float*)d_in[4];
    const float* W_ctx     = (const float*)d_in[5];
    const float* b_ctx     = (const float*)d_in[6];
    const float* W_h2a     = (const float*)d_in[7];
    const float* b_h2a     = (const float*)d_in[8];
    const float* W_alpha   = (const float*)d_in[9];
    const float* b_alpha   = (const float*)d_in[10];
    const float* W_ih      = (const float*)d_in[11];
    const float* W_hh      = (const float*)d_in[12];
    float* out = (float*)d_out;

    cudaFuncSetAttribute(att_score_mma,
                         cudaFuncAttributeMaxDynamicSharedMemorySize,
                         2 * STGB);

    att_h_kernel<<<dim3(AH / 64, B_ / 64), 256>>>(h0, W_h2a, b_h2a, b_ctx);
    att_score_mma<<<dim3(AH / TN, BL / TM), 256, 2 * STGB>>>(att_feats, W_ctx, W_alpha);
    softmax_kernel<<<B_, 256>>>(b_alpha);
    att_res_kernel<<<B_, 256>>>(att_feats);
    gates_kernel<<<dim3(4 * RS / 128, B_ / 128), 256>>>(xt, h0, W_ih, W_hh);
    lstm_kernel<<<(B_ * RS + 255) / 256, 256>>>(c0, out, out_size);
}

// round 14
// speedup vs baseline: 2.3720x; 1.9121x over previous
#include <cuda_runtime.h>
#include <cuda_fp16.h>
#include <stdint.h>
#include <cstdint>
#include <math.h>

#define B_  256
#define L_  196
#define AF  2048   // ATT_FEAT
#define AH  512    // ATT_HID
#define RS  512    // RNN_SIZE
#define IE  512    // INPUT_ENC
#define BL  (B_*L_)   // 50176

// ---------------- scratch (device globals; no allocation allowed) ----------
__device__ __half g_a16[(size_t)BL*AF];   // fp16 copy of att_feats (196 MB)
__device__ __half g_w16[AH*AF];           // fp16 copy of W_ctx
__device__ float g_att_h[B_*AH];          // h0@W_h2a.T + b_h2a + b_ctx
__device__ float g_scores_part[4*BL];     // per col-block partial scores
__device__ float g_weight[B_*L_];
__device__ float g_att_res[B_*AF];
__device__ float g_gates[B_*4*RS];

// ======================= helpers ==========================================
__device__ __forceinline__ uint32_t smem_u32(const void* p) {
    uint32_t a;
    asm("{ .reg .u64 t; cvta.to.shared.u64 t, %1; cvt.u32.u64 %0, t; }"
        : "=r"(a) : "l"(p));
    return a;
}

#define SWZ(o) ((o) ^ (((o) >> 3) & 0x70))

#define CPASYNC16(dst, src)                                                  \
    asm volatile("cp.async.cg.shared.global [%0], [%1], 16;"                 \
                 :: "r"(dst), "l"(src))
#define CPCOMMIT() asm volatile("cp.async.commit_group;" ::: "memory")
#define CPWAIT1()  asm volatile("cp.async.wait_group 1;" ::: "memory")

#define LDMX4(r0, r1, r2, r3, addr)                                          \
    asm volatile("ldmatrix.sync.aligned.m8n8.x4.shared.b16 {%0,%1,%2,%3}, [%4];" \
                 : "=r"(r0), "=r"(r1), "=r"(r2), "=r"(r3) : "r"(addr))

#define MMA16816(c, a, b0, b1)                                               \
    asm volatile("mma.sync.aligned.m16n8k16.row.col.f32.f16.f16.f32 "        \
                 "{%0,%1,%2,%3}, {%4,%5,%6,%7}, {%8,%9}, {%0,%1,%2,%3};"     \
                 : "+f"((c)[0]), "+f"((c)[1]), "+f"((c)[2]), "+f"((c)[3])    \
                 : "r"((a)[0]), "r"((a)[1]), "r"((a)[2]), "r"((a)[3]),       \
                   "r"(b0), "r"(b1))

// ---------------- fp32 -> fp16 streaming converters ------------------------
__global__ __launch_bounds__(256)
void cvtA_kernel(const float* __restrict__ src) {
    size_t i = ((size_t)blockIdx.x * 256 + threadIdx.x) * 4;
    float4 v = *(const float4*)&src[i];
    __half2 h0 = __floats2half2_rn(v.x, v.y);
    __half2 h1 = __floats2half2_rn(v.z, v.w);
    uint2 r;
    r.x = *(uint32_t*)&h0;
    r.y = *(uint32_t*)&h1;
    *(uint2*)&g_a16[i] = r;
}
__global__ __launch_bounds__(256)
void cvtW_kernel(const float* __restrict__ src) {
    size_t i = ((size_t)blockIdx.x * 256 + threadIdx.x) * 4;
    float4 v = *(const float4*)&src[i];
    __half2 h0 = __floats2half2_rn(v.x, v.y);
    __half2 h1 = __floats2half2_rn(v.z, v.w);
    uint2 r;
    r.x = *(uint32_t*)&h0;
    r.y = *(uint32_t*)&h1;
    *(uint2*)&g_w16[i] = r;
}

// ================= cp.async pipelined fp16 GEMM + fused score ==============
// D[m,h] = sum_k A[m,k]*Wc[h,k];  p[m] = sum_h W_alpha[h]*tanh(D + att_h)
#define TM 128
#define TN 128
#define TKH 64                  // fp16 K per stage (128 bytes/row)
#define TILEB 16384             // 128 rows * 128 B
#define STG (2*TILEB)           // A + B = 32 KB per stage
#define STAGES 3
#define NSTG (AF / TKH)         // 32

__global__ void __launch_bounds__(256, 2)
att_score_mma(const float* __restrict__ W_alpha)
{
    extern __shared__ char dsm[];
    __shared__ float red[TM][2];
    const int tid  = threadIdx.x;
    const int lane = tid & 31, wid = tid >> 5;
    const int warp_m = wid & 3, warp_n = wid >> 2;
    const int row0 = blockIdx.y * TM;
    const int n0   = blockIdx.x * TN;
    const uint32_t sb = smem_u32(dsm);

    // per-thread cp.async chunk: 1024 16B-chunks per tile, 4 per thread
    const int chr = tid >> 3;            // base row (0..31), rows chr+32*i
    const int chc = tid & 7;             // 16B column (0..7)
    const __half* Abase = g_a16 + (size_t)(row0 + chr) * AF + chc * 8;
    const __half* Bbase = g_w16 + (size_t)(n0 + chr) * AF + chc * 8;
    const uint32_t dsto = SWZ((uint32_t)(chr * 128 + chc * 16));

    float cfr[2][8][4];
    #pragma unroll
    for (int mt = 0; mt < 2; mt++)
        #pragma unroll
        for (int nt = 0; nt < 8; nt++)
            #pragma unroll
            for (int j = 0; j < 4; j++) cfr[mt][nt][j] = 0.f;

    // issue stage ks into slot ks%3
    #define ISSUE(ks) do {                                                    \
        uint32_t _b = sb + ((ks) % 3) * STG;                                  \
        const __half* _a = Abase + (ks) * TKH;                                \
        const __half* _w = Bbase + (ks) * TKH;                                \
        _Pragma("unroll")                                                     \
        for (int _i = 0; _i < 4; _i++) {                                      \
            uint32_t _d = dsto + (uint32_t)(_i * 32 * 128);                   \
            CPASYNC16(_b + _d, _a + (size_t)(_i * 32) * AF);                  \
            CPASYNC16(_b + TILEB + _d, _w + (size_t)(_i * 32) * AF);          \
        }                                                                     \
    } while (0)

    ISSUE(0); CPCOMMIT();
    ISSUE(1); CPCOMMIT();

    const uint32_t lrow = lane & 15;
    const uint32_t loff = (uint32_t)((lane >> 4) & 1) * 16;  // 0 / 16 bytes

    for (int ks = 0; ks < NSTG; ks++) {
        CPWAIT1();
        __syncthreads();
        if (ks + 2 < NSTG) ISSUE(ks + 2);
        CPCOMMIT();

        const uint32_t base = sb + (ks % 3) * STG;
        #pragma unroll
        for (int kk = 0; kk < 4; kk++) {
            const uint32_t acol = (uint32_t)kk * 32 + loff;
            uint32_t af[2][4], bf[4][4];
            #pragma unroll
            for (int mt = 0; mt < 2; mt++) {
                uint32_t r = (uint32_t)(warp_m * 32 + mt * 16 + lrow);
                LDMX4(af[mt][0], af[mt][1], af[mt][2], af[mt][3],
                      base + SWZ(r * 128 + acol));
            }
            #pragma unroll
            for (int ng = 0; ng < 4; ng++) {
                uint32_t r = (uint32_t)(warp_n * 64 + ng * 16 + lrow);
                LDMX4(bf[ng][0], bf[ng][1], bf[ng][2], bf[ng][3],
                      base + TILEB + SWZ(r * 128 + acol));
            }
            #pragma unroll
            for (int mt = 0; mt < 2; mt++)
                #pragma unroll
                for (int nt = 0; nt < 8; nt++) {
                    int ng = nt >> 1, od = nt & 1;
                    MMA16816(cfr[mt][nt], af[mt],
                             bf[ng][od ? 1 : 0], bf[ng][od ? 3 : 2]);
                }
        }
    }

    // ---- epilogue: tanh + dot W_alpha, reduce to per-row partials ----
    __syncthreads();
    const int g = lane >> 2, tg = lane & 3;
    #pragma unroll
    for (int mt = 0; mt < 2; mt++) {
        int lr0 = warp_m * 32 + mt * 16 + g;
        int grow0 = row0 + lr0;
        int bb0 = grow0 / L_;
        int bb1 = (grow0 + 8) / L_;
        const float* ah0 = &g_att_h[bb0 * AH + n0];
        const float* ah1 = &g_att_h[bb1 * AH + n0];
        float p0 = 0.f, p1 = 0.f;
        #pragma unroll
        for (int nt = 0; nt < 8; nt++) {
            int col = warp_n * 64 + nt * 8 + tg * 2;
            float wa0 = __ldg(&W_alpha[n0 + col]);
            float wa1 = __ldg(&W_alpha[n0 + col + 1]);
            p0 += wa0 * tanhf(cfr[mt][nt][0] + __ldg(&ah0[col]))
                + wa1 * tanhf(cfr[mt][nt][1] + __ldg(&ah0[col + 1]));
            p1 += wa0 * tanhf(cfr[mt][nt][2] + __ldg(&ah1[col]))
                + wa1 * tanhf(cfr[mt][nt][3] + __ldg(&ah1[col + 1]));
        }
        p0 += __shfl_xor_sync(0xFFFFFFFFu, p0, 1);
        p0 += __shfl_xor_sync(0xFFFFFFFFu, p0, 2);
        p1 += __shfl_xor_sync(0xFFFFFFFFu, p1, 1);
        p1 += __shfl_xor_sync(0xFFFFFFFFu, p1, 2);
        if (tg == 0) {
            red[lr0][warp_n]     = p0;
            red[lr0 + 8][warp_n] = p1;
        }
    }
    __syncthreads();
    if (tid < TM)
        g_scores_part[(size_t)blockIdx.x * BL + row0 + tid] = red[tid][0] + red[tid][1];
}

// ---------------- small GEMM: att_h = h0 @ W_h2a.T + b_h2a + b_ctx ---------
__global__ __launch_bounds__(256)
void att_h_kernel(const float* __restrict__ h0,
                  const float* __restrict__ W_h2a,
                  const float* __restrict__ b_h2a,
                  const float* __restrict__ b_ctx)
{
    const int BM = 64, BN = 64, BK = 16;
    __shared__ float As[BK][BM + 4];
    __shared__ float Bs[BK][BN + 4];
    int tid = threadIdx.x;
    int tx = tid & 15, ty = tid >> 4;
    int row0 = blockIdx.y * BM;
    int col0 = blockIdx.x * BN;
    float acc[4][4] = {};

    for (int k0 = 0; k0 < RS; k0 += BK) {
        int m  = tid >> 2;
        int kk = (tid & 3) * 4;
        float4 va = *(const float4*)&h0[(row0 + m) * RS + k0 + kk];
        As[kk + 0][m] = va.x; As[kk + 1][m] = va.y;
        As[kk + 2][m] = va.z; As[kk + 3][m] = va.w;
        float4 vb = *(const float4*)&W_h2a[(col0 + m) * RS + k0 + kk];
        Bs[kk + 0][m] = vb.x; Bs[kk + 1][m] = vb.y;
        Bs[kk + 2][m] = vb.z; Bs[kk + 3][m] = vb.w;
        __syncthreads();
        #pragma unroll
        for (int k = 0; k < BK; k++) {
            float a[4], b[4];
            *(float4*)a = *(const float4*)&As[k][ty * 4];
            *(float4*)b = *(const float4*)&Bs[k][tx * 4];
            #pragma unroll
            for (int i = 0; i < 4; i++)
                #pragma unroll
                for (int j = 0; j < 4; j++)
                    acc[i][j] = fmaf(a[i], b[j], acc[i][j]);
        }
        __syncthreads();
    }
    #pragma unroll
    for (int i = 0; i < 4; i++) {
        int r = row0 + ty * 4 + i;
        #pragma unroll
        for (int j = 0; j < 4; j++) {
            int c = col0 + tx * 4 + j;
            g_att_h[r * AH + c] = acc[i][j] + b_h2a[c] + b_ctx[c];
        }
    }
}

// ---------------- softmax over L per batch --------------------------------
__global__ void softmax_kernel(const float* __restrict__ b_alpha)
{
    int b = blockIdx.x;
    int t = threadIdx.x;   // 256
    __shared__ float sm[256];
    float v = 0.f;
    float s = -1e30f;
    if (t < L_) {
        int idx = b * L_ + t;
        v = g_scores_part[idx] + g_scores_part[BL + idx] +
            g_scores_part[2 * BL + idx] + g_scores_part[3 * BL + idx] +
            b_alpha[0];
        s = v;
    }
    sm[t] = s; __syncthreads();
    for (int o = 128; o > 0; o >>= 1) {
        if (t < o) sm[t] = fmaxf(sm[t], sm[t + o]);
        __syncthreads();
    }
    float mx = sm[0];
    __syncthreads();
    float e = (t < L_) ? expf(v - mx) : 0.f;
    sm[t] = e; __syncthreads();
    for (int o = 128; o > 0; o >>= 1) {
        if (t < o) sm[t] += sm[t + o];
        __syncthreads();
    }
    float inv = 1.f / sm[0];
    if (t < L_) g_weight[b * L_ + t] = e * inv;
}

// ---------------- att_res = weight @ att_feats (fp16 copy, mem-bound) ------
__global__ __launch_bounds__(256)
void att_res_kernel()
{
    int b = blockIdx.x;
    int t = threadIdx.x;  // 256
    __shared__ float ws[L_];
    if (t < L_) ws[t] = g_weight[b * L_ + t];
    __syncthreads();
    const __half* base = g_a16 + (size_t)b * L_ * AF;
    int c0 = t * 8;     // 8 cols per thread = 16 bytes
    float acc[8] = {};
    for (int l = 0; l < L_; l++) {
        float w = ws[l];
        uint4 raw = *(const uint4*)(base + (size_t)l * AF + c0);
        __half2 h01 = *(__half2*)&raw.x;
        __half2 h23 = *(__half2*)&raw.y;
        __half2 h45 = *(__half2*)&raw.z;
        __half2 h67 = *(__half2*)&raw.w;
        float2 f01 = __half22float2(h01);
        float2 f23 = __half22float2(h23);
        float2 f45 = __half22float2(h45);
        float2 f67 = __half22float2(h67);
        acc[0] = fmaf(w, f01.x, acc[0]); acc[1] = fmaf(w, f01.y, acc[1]);
        acc[2] = fmaf(w, f23.x, acc[2]); acc[3] = fmaf(w, f23.y, acc[3]);
        acc[4] = fmaf(w, f45.x, acc[4]); acc[5] = fmaf(w, f45.y, acc[5]);
        acc[6] = fmaf(w, f67.x, acc[6]); acc[7] = fmaf(w, f67.y, acc[7]);
    }
    *(float4*)&g_att_res[b * AF + c0]     = *(float4*)&acc[0];
    *(float4*)&g_att_res[b * AF + c0 + 4] = *(float4*)&acc[4];
}

// ---------------- gates GEMM: [xt|att_res|h0] @ [W_ih|W_hh].T -------------
__device__ __forceinline__ float4 load_Ag(const float* xt, const float* h0,
                                          int row, int k)
{
    if (k < IE)           return *(const float4*)&xt[row * IE + k];
    else if (k < IE + AF) return *(const float4*)&g_att_res[row * AF + (k - IE)];
    else                  return *(const float4*)&h0[row * RS + (k - IE - AF)];
}
__device__ __forceinline__ float4 load_Bg(const float* W_ih, const float* W_hh,
                                          int col, int k)
{
    if (k < IE + AF) return *(const float4*)&W_ih[(size_t)col * (IE + AF) + k];
    else             return *(const float4*)&W_hh[col * RS + (k - IE - AF)];
}

__global__ __launch_bounds__(256)
void gates_kernel(const float* __restrict__ xt,
                  const float* __restrict__ h0,
                  const float* __restrict__ W_ih,
                  const float* __restrict__ W_hh)
{
    const int BM = 64, BN = 128, BK = 16, KK = IE + AF + RS; // 3072
    __shared__ float As[BK][BM + 4];
    __shared__ float Bs[BK][BN + 4];
    int tid = threadIdx.x;
    int tx = tid & 15, ty = tid >> 4;
    int row0 = blockIdx.y * BM;
    int col0 = blockIdx.x * BN;
    float acc[4][8] = {};

    for (int k0 = 0; k0 < KK; k0 += BK) {
        {
            int m  = tid >> 2;
            int kk = (tid & 3) * 4;
            float4 va = load_Ag(xt, h0, row0 + m, k0 + kk);
            As[kk + 0][m] = va.x; As[kk + 1][m] = va.y;
            As[kk + 2][m] = va.z; As[kk + 3][m] = va.w;
        }
        #pragma unroll
        for (int i = 0; i < 2; i++) {
            int e  = tid + i * 256;
            int m  = e >> 2;
            int kk = (e & 3) * 4;
            float4 vb = load_Bg(W_ih, W_hh, col0 + m, k0 + kk);
            Bs[kk + 0][m] = vb.x; Bs[kk + 1][m] = vb.y;
            Bs[kk + 2][m] = vb.z; Bs[kk + 3][m] = vb.w;
        }
        __syncthreads();
        #pragma unroll
        for (int k = 0; k < BK; k++) {
            float a[4], b[8];
            *(float4*)&a[0] = *(const float4*)&As[k][ty * 4];
            *(float4*)&b[0] = *(const float4*)&Bs[k][tx * 8];
            *(float4*)&b[4] = *(const float4*)&Bs[k][tx * 8 + 4];
            #pragma unroll
            for (int i = 0; i < 4; i++)
                #pragma unroll
                for (int j = 0; j < 8; j++)
                    acc[i][j] = fmaf(a[i], b[j], acc[i][j]);
        }
        __syncthreads();
    }
    #pragma unroll
    for (int i = 0; i < 4; i++) {
        int r = row0 + ty * 4 + i;
        #pragma unroll
        for (int j = 0; j < 8; j++) {
            int c = col0 + tx * 8 + j;
            g_gates[r * (4 * RS) + c] = acc[i][j];
        }
    }
}

// ---------------- LSTM pointwise + output writes --------------------------
__global__ void lstm_kernel(const float* __restrict__ c0,
                            float* __restrict__ out, int out_size)
{
    int idx = blockIdx.x * 256 + threadIdx.x;
    if (idx >= B_ * RS) return;
    int b = idx / RS, j = idx % RS;
    const float* g = &g_gates[b * 4 * RS];
    float i_ = 1.f / (1.f + expf(-g[j]));
    float f_ = 1.f / (1.f + expf(-g[RS + j]));
    float gg = tanhf(g[2 * RS + j]);
    float o_ = 1.f / (1.f + expf(-g[3 * RS + j]));
    float c  = f_ * c0[idx] + i_ * gg;
    float h  = o_ * tanhf(c);
    out[idx] = h;
    if (out_size >= 3 * B_ * RS) {
        out[B_ * RS + idx]     = h;   // h_new[None]
        out[2 * B_ * RS + idx] = c;   // c_new[None]
    }
}

// ---------------- launch ---------------------------------------------------
extern "C" void kernel_launch(void* const* d_in, const int* in_sizes, int n_in,
                              void* d_out, int out_size)
{
    const float* xt        = (const float*)d_in[0];
    // d_in[1] = fc_feats (unused by reference)
    const float* att_feats = (const float*)d_in[2];
    const float* h0        = (const float*)d_in[3];
    const float* c0        = (const float*)d_in[4];
    const float* W_ctx     = (const float*)d_in[5];
    const float* b_ctx     = (const float*)d_in[6];
    const float* W_h2a     = (const float*)d_in[7];
    const float* b_h2a     = (const float*)d_in[8];
    const float* W_alpha   = (const float*)d_in[9];
    const float* b_alpha   = (const float*)d_in[10];
    const float* W_ih      = (const float*)d_in[11];
    const float* W_hh      = (const float*)d_in[12];
    float* out = (float*)d_out;

    cudaFuncSetAttribute(att_score_mma,
                         cudaFuncAttributeMaxDynamicSharedMemorySize,
                         STAGES * STG);

    cvtA_kernel<<<(int)(((size_t)BL * AF) / 1024), 256>>>(att_feats);
    cvtW_kernel<<<(AH * AF) / 1024, 256>>>(W_ctx);
    att_h_kernel<<<dim3(AH / 64, B_ / 64), 256>>>(h0, W_h2a, b_h2a, b_ctx);
    att_score_mma<<<dim3(AH / TN, BL / TM), 256, STAGES * STG>>>(W_alpha);
    softmax_kernel<<<B_, 256>>>(b_alpha);
    att_res_kernel<<<B_, 256>>>();
    gates_kernel<<<dim3(4 * RS / 128, B_ / 64), 256>>>(xt, h0, W_ih, W_hh);
    lstm_kernel<<<(B_ * RS + 255) / 256, 256>>>(c0, out, out_size);
}

// round 17
// speedup vs baseline: 2.6605x; 1.1216x over previous
#include <cuda_runtime.h>
#include <cuda_fp16.h>
#include <stdint.h>
#include <cstdint>
#include <math.h>

#define B_  256
#define L_  196
#define AF  2048   // ATT_FEAT
#define AH  512    // ATT_HID
#define RS  512    // RNN_SIZE
#define IE  512    // INPUT_ENC
#define BL  (B_*L_)   // 50176

// ---------------- scratch (device globals; no allocation allowed) ----------
__device__ __half g_a16[(size_t)BL*AF];   // fp16 copy of att_feats (196 MB)
__device__ __half g_w16[AH*AF];           // fp16 copy of W_ctx
__device__ float g_att_h[B_*AH];          // h0@W_h2a.T + b_h2a + b_ctx
__device__ float g_scores_part[4*BL];     // per col-block partial scores
__device__ float g_att_res[B_*AF];
__device__ float g_gates[B_*4*RS];

// ======================= helpers ==========================================
__device__ __forceinline__ uint32_t smem_u32(const void* p) {
    uint32_t a;
    asm("{ .reg .u64 t; cvta.to.shared.u64 t, %1; cvt.u32.u64 %0, t; }"
        : "=r"(a) : "l"(p));
    return a;
}

#define SWZ(o) ((o) ^ (((o) >> 3) & 0x70))

#define CPASYNC16(dst, src)                                                  \
    asm volatile("cp.async.cg.shared.global [%0], [%1], 16;"                 \
                 :: "r"(dst), "l"(src))
#define CPCOMMIT() asm volatile("cp.async.commit_group;" ::: "memory")
#define CPWAIT1()  asm volatile("cp.async.wait_group 1;" ::: "memory")

#define LDMX4(r0, r1, r2, r3, addr)                                          \
    asm volatile("ldmatrix.sync.aligned.m8n8.x4.shared.b16 {%0,%1,%2,%3}, [%4];" \
                 : "=r"(r0), "=r"(r1), "=r"(r2), "=r"(r3) : "r"(addr))

#define MMA16816(c, a, b0, b1)                                               \
    asm volatile("mma.sync.aligned.m16n8k16.row.col.f32.f16.f16.f32 "        \
                 "{%0,%1,%2,%3}, {%4,%5,%6,%7}, {%8,%9}, {%0,%1,%2,%3};"     \
                 : "+f"((c)[0]), "+f"((c)[1]), "+f"((c)[2]), "+f"((c)[3])    \
                 : "r"((a)[0]), "r"((a)[1]), "r"((a)[2]), "r"((a)[3]),       \
                   "r"(b0), "r"(b1))

// ---------------- fp32 -> fp16 streaming converters ------------------------
__global__ __launch_bounds__(256)
void cvtA_kernel(const float* __restrict__ src) {
    size_t i = ((size_t)blockIdx.x * 256 + threadIdx.x) * 4;
    float4 v = *(const float4*)&src[i];
    __half2 h0 = __floats2half2_rn(v.x, v.y);
    __half2 h1 = __floats2half2_rn(v.z, v.w);
    uint2 r;
    r.x = *(uint32_t*)&h0;
    r.y = *(uint32_t*)&h1;
    *(uint2*)&g_a16[i] = r;
}
__global__ __launch_bounds__(256)
void cvtW_kernel(const float* __restrict__ src) {
    size_t i = ((size_t)blockIdx.x * 256 + threadIdx.x) * 4;
    float4 v = *(const float4*)&src[i];
    __half2 h0 = __floats2half2_rn(v.x, v.y);
    __half2 h1 = __floats2half2_rn(v.z, v.w);
    uint2 r;
    r.x = *(uint32_t*)&h0;
    r.y = *(uint32_t*)&h1;
    *(uint2*)&g_w16[i] = r;
}

// ================= cp.async pipelined fp16 GEMM + fused score ==============
// D[m,h] = sum_k A[m,k]*Wc[h,k];  p[m] = sum_h W_alpha[h]*tanh(D + att_h)
#define TM 128
#define TN 128
#define TKH 64                  // fp16 K per stage (128 bytes/row)
#define TILEB 16384             // 128 rows * 128 B
#define STG (2*TILEB)           // A + B = 32 KB per stage
#define STAGES 3
#define NSTG (AF / TKH)         // 32

__global__ void __launch_bounds__(256, 2)
att_score_mma(const float* __restrict__ W_alpha)
{
    extern __shared__ char dsm[];
    __shared__ float red[TM][2];
    const int tid  = threadIdx.x;
    const int lane = tid & 31, wid = tid >> 5;
    const int warp_m = wid & 3, warp_n = wid >> 2;
    const int row0 = blockIdx.y * TM;
    const int n0   = blockIdx.x * TN;
    const uint32_t sb = smem_u32(dsm);

    // per-thread cp.async chunk: 1024 16B-chunks per tile, 4 per thread
    const int chr = tid >> 3;            // base row (0..31), rows chr+32*i
    const int chc = tid & 7;             // 16B column (0..7)
    const __half* Abase = g_a16 + (size_t)(row0 + chr) * AF + chc * 8;
    const __half* Bbase = g_w16 + (size_t)(n0 + chr) * AF + chc * 8;
    const uint32_t dsto = SWZ((uint32_t)(chr * 128 + chc * 16));

    float cfr[2][8][4];
    #pragma unroll
    for (int mt = 0; mt < 2; mt++)
        #pragma unroll
        for (int nt = 0; nt < 8; nt++)
            #pragma unroll
            for (int j = 0; j < 4; j++) cfr[mt][nt][j] = 0.f;

    // issue stage ks into slot ks%3
    #define ISSUE(ks) do {                                                    \
        uint32_t _b = sb + ((ks) % 3) * STG;                                  \
        const __half* _a = Abase + (ks) * TKH;                                \
        const __half* _w = Bbase + (ks) * TKH;                                \
        _Pragma("unroll")                                                     \
        for (int _i = 0; _i < 4; _i++) {                                      \
            uint32_t _d = dsto + (uint32_t)(_i * 32 * 128);                   \
            CPASYNC16(_b + _d, _a + (size_t)(_i * 32) * AF);                  \
            CPASYNC16(_b + TILEB + _d, _w + (size_t)(_i * 32) * AF);          \
        }                                                                     \
    } while (0)

    ISSUE(0); CPCOMMIT();
    ISSUE(1); CPCOMMIT();

    const uint32_t lrow = lane & 15;
    const uint32_t loff = (uint32_t)((lane >> 4) & 1) * 16;  // 0 / 16 bytes

    for (int ks = 0; ks < NSTG; ks++) {
        CPWAIT1();
        __syncthreads();
        if (ks + 2 < NSTG) ISSUE(ks + 2);
        CPCOMMIT();

        const uint32_t base = sb + (ks % 3) * STG;
        #pragma unroll
        for (int kk = 0; kk < 4; kk++) {
            const uint32_t acol = (uint32_t)kk * 32 + loff;
            uint32_t af[2][4], bf[4][4];
            #pragma unroll
            for (int mt = 0; mt < 2; mt++) {
                uint32_t r = (uint32_t)(warp_m * 32 + mt * 16 + lrow);
                LDMX4(af[mt][0], af[mt][1], af[mt][2], af[mt][3],
                      base + SWZ(r * 128 + acol));
            }
            #pragma unroll
            for (int ng = 0; ng < 4; ng++) {
                uint32_t r = (uint32_t)(warp_n * 64 + ng * 16 + lrow);
                LDMX4(bf[ng][0], bf[ng][1], bf[ng][2], bf[ng][3],
                      base + TILEB + SWZ(r * 128 + acol));
            }
            #pragma unroll
            for (int mt = 0; mt < 2; mt++)
                #pragma unroll
                for (int nt = 0; nt < 8; nt++) {
                    int ng = nt >> 1, od = nt & 1;
                    MMA16816(cfr[mt][nt], af[mt],
                             bf[ng][od ? 1 : 0], bf[ng][od ? 3 : 2]);
                }
        }
    }

    // ---- epilogue: tanh + dot W_alpha, reduce to per-row partials ----
    __syncthreads();
    const int g = lane >> 2, tg = lane & 3;
    #pragma unroll
    for (int mt = 0; mt < 2; mt++) {
        int lr0 = warp_m * 32 + mt * 16 + g;
        int grow0 = row0 + lr0;
        int bb0 = grow0 / L_;
        int bb1 = (grow0 + 8) / L_;
        const float* ah0 = &g_att_h[bb0 * AH + n0];
        const float* ah1 = &g_att_h[bb1 * AH + n0];
        float p0 = 0.f, p1 = 0.f;
        #pragma unroll
        for (int nt = 0; nt < 8; nt++) {
            int col = warp_n * 64 + nt * 8 + tg * 2;
            float wa0 = __ldg(&W_alpha[n0 + col]);
            float wa1 = __ldg(&W_alpha[n0 + col + 1]);
            p0 += wa0 * tanhf(cfr[mt][nt][0] + __ldg(&ah0[col]))
                + wa1 * tanhf(cfr[mt][nt][1] + __ldg(&ah0[col + 1]));
            p1 += wa0 * tanhf(cfr[mt][nt][2] + __ldg(&ah1[col]))
                + wa1 * tanhf(cfr[mt][nt][3] + __ldg(&ah1[col + 1]));
        }
        p0 += __shfl_xor_sync(0xFFFFFFFFu, p0, 1);
        p0 += __shfl_xor_sync(0xFFFFFFFFu, p0, 2);
        p1 += __shfl_xor_sync(0xFFFFFFFFu, p1, 1);
        p1 += __shfl_xor_sync(0xFFFFFFFFu, p1, 2);
        if (tg == 0) {
            red[lr0][warp_n]     = p0;
            red[lr0 + 8][warp_n] = p1;
        }
    }
    __syncthreads();
    if (tid < TM)
        g_scores_part[(size_t)blockIdx.x * BL + row0 + tid] = red[tid][0] + red[tid][1];
}

// ---------------- small GEMM: att_h = h0 @ W_h2a.T + b_h2a + b_ctx ---------
__global__ __launch_bounds__(256)
void att_h_kernel(const float* __restrict__ h0,
                  const float* __restrict__ W_h2a,
                  const float* __restrict__ b_h2a,
                  const float* __restrict__ b_ctx)
{
    const int BM = 64, BN = 64, BK = 16;
    __shared__ float As[BK][BM + 4];
    __shared__ float Bs[BK][BN + 4];
    int tid = threadIdx.x;
    int tx = tid & 15, ty = tid >> 4;
    int row0 = blockIdx.y * BM;
    int col0 = blockIdx.x * BN;
    float acc[4][4] = {};

    for (int k0 = 0; k0 < RS; k0 += BK) {
        int m  = tid >> 2;
        int kk = (tid & 3) * 4;
        float4 va = *(const float4*)&h0[(row0 + m) * RS + k0 + kk];
        As[kk + 0][m] = va.x; As[kk + 1][m] = va.y;
        As[kk + 2][m] = va.z; As[kk + 3][m] = va.w;
        float4 vb = *(const float4*)&W_h2a[(col0 + m) * RS + k0 + kk];
        Bs[kk + 0][m] = vb.x; Bs[kk + 1][m] = vb.y;
        Bs[kk + 2][m] = vb.z; Bs[kk + 3][m] = vb.w;
        __syncthreads();
        #pragma unroll
        for (int k = 0; k < BK; k++) {
            float a[4], b[4];
            *(float4*)a = *(const float4*)&As[k][ty * 4];
            *(float4*)b = *(const float4*)&Bs[k][tx * 4];
            #pragma unroll
            for (int i = 0; i < 4; i++)
                #pragma unroll
                for (int j = 0; j < 4; j++)
                    acc[i][j] = fmaf(a[i], b[j], acc[i][j]);
        }
        __syncthreads();
    }
    #pragma unroll
    for (int i = 0; i < 4; i++) {
        int r = row0 + ty * 4 + i;
        #pragma unroll
        for (int j = 0; j < 4; j++) {
            int c = col0 + tx * 4 + j;
            g_att_h[r * AH + c] = acc[i][j] + b_h2a[c] + b_ctx[c];
        }
    }
}

// -------- fused softmax + att_res (per-batch block, fp16 feats) -----------
__global__ __launch_bounds__(256)
void softmax_attres_kernel(const float* __restrict__ b_alpha)
{
    int b = blockIdx.x;
    int t = threadIdx.x;   // 256
    __shared__ float sm[256];
    __shared__ float ws[L_];

    // softmax over L
    float v = 0.f;
    float s = -1e30f;
    if (t < L_) {
        int idx = b * L_ + t;
        v = g_scores_part[idx] + g_scores_part[BL + idx] +
            g_scores_part[2 * BL + idx] + g_scores_part[3 * BL + idx] +
            b_alpha[0];
        s = v;
    }
    sm[t] = s; __syncthreads();
    for (int o = 128; o > 0; o >>= 1) {
        if (t < o) sm[t] = fmaxf(sm[t], sm[t + o]);
        __syncthreads();
    }
    float mx = sm[0];
    __syncthreads();
    float e = (t < L_) ? expf(v - mx) : 0.f;
    sm[t] = e; __syncthreads();
    for (int o = 128; o > 0; o >>= 1) {
        if (t < o) sm[t] += sm[t + o];
        __syncthreads();
    }
    float inv = 1.f / sm[0];
    if (t < L_) ws[t] = e * inv;
    __syncthreads();

    // att_res = weight @ att_feats (fp16 copy)
    const __half* base = g_a16 + (size_t)b * L_ * AF;
    int c0 = t * 8;     // 8 cols per thread = 16 bytes
    float acc[8] = {};
    for (int l = 0; l < L_; l++) {
        float w = ws[l];
        uint4 raw = *(const uint4*)(base + (size_t)l * AF + c0);
        __half2 h01 = *(__half2*)&raw.x;
        __half2 h23 = *(__half2*)&raw.y;
        __half2 h45 = *(__half2*)&raw.z;
        __half2 h67 = *(__half2*)&raw.w;
        float2 f01 = __half22float2(h01);
        float2 f23 = __half22float2(h23);
        float2 f45 = __half22float2(h45);
        float2 f67 = __half22float2(h67);
        acc[0] = fmaf(w, f01.x, acc[0]); acc[1] = fmaf(w, f01.y, acc[1]);
        acc[2] = fmaf(w, f23.x, acc[2]); acc[3] = fmaf(w, f23.y, acc[3]);
        acc[4] = fmaf(w, f45.x, acc[4]); acc[5] = fmaf(w, f45.y, acc[5]);
        acc[6] = fmaf(w, f67.x, acc[6]); acc[7] = fmaf(w, f67.y, acc[7]);
    }
    *(float4*)&g_att_res[b * AF + c0]     = *(float4*)&acc[0];
    *(float4*)&g_att_res[b * AF + c0 + 4] = *(float4*)&acc[4];
}

// ---------------- gates GEMM: [xt|att_res|h0] @ [W_ih|W_hh].T -------------
__device__ __forceinline__ float4 load_Ag(const float* xt, const float* h0,
                                          int row, int k)
{
    if (k < IE)           return *(const float4*)&xt[row * IE + k];
    else if (k < IE + AF) return *(const float4*)&g_att_res[row * AF + (k - IE)];
    else                  return *(const float4*)&h0[row * RS + (k - IE - AF)];
}
__device__ __forceinline__ float4 load_Bg(const float* W_ih, const float* W_hh,
                                          int col, int k)
{
    if (k < IE + AF) return *(const float4*)&W_ih[(size_t)col * (IE + AF) + k];
    else             return *(const float4*)&W_hh[col * RS + (k - IE - AF)];
}

__global__ __launch_bounds__(256)
void gates_kernel(const float* __restrict__ xt,
                  const float* __restrict__ h0,
                  const float* __restrict__ W_ih,
                  const float* __restrict__ W_hh)
{
    const int BM = 64, BN = 64, BK = 16, KK = IE + AF + RS; // 3072
    __shared__ float As[BK][BM + 4];
    __shared__ float Bs[BK][BN + 4];
    int tid = threadIdx.x;
    int tx = tid & 15, ty = tid >> 4;
    int row0 = blockIdx.y * BM;
    int col0 = blockIdx.x * BN;
    float acc[4][4] = {};

    for (int k0 = 0; k0 < KK; k0 += BK) {
        int m  = tid >> 2;
        int kk = (tid & 3) * 4;
        float4 va = load_Ag(xt, h0, row0 + m, k0 + kk);
        As[kk + 0][m] = va.x; As[kk + 1][m] = va.y;
        As[kk + 2][m] = va.z; As[kk + 3][m] = va.w;
        float4 vb = load_Bg(W_ih, W_hh, col0 + m, k0 + kk);
        Bs[kk + 0][m] = vb.x; Bs[kk + 1][m] = vb.y;
        Bs[kk + 2][m] = vb.z; Bs[kk + 3][m] = vb.w;
        __syncthreads();
        #pragma unroll
        for (int k = 0; k < BK; k++) {
            float a[4], b[4];
            *(float4*)&a[0] = *(const float4*)&As[k][ty * 4];
            *(float4*)&b[0] = *(const float4*)&Bs[k][tx * 4];
            #pragma unroll
            for (int i = 0; i < 4; i++)
                #pragma unroll
                for (int j = 0; j < 4; j++)
                    acc[i][j] = fmaf(a[i], b[j], acc[i][j]);
        }
        __syncthreads();
    }
    #pragma unroll
    for (int i = 0; i < 4; i++) {
        int r = row0 + ty * 4 + i;
        #pragma unroll
        for (int j = 0; j < 4; j++) {
            int c = col0 + tx * 4 + j;
            g_gates[r * (4 * RS) + c] = acc[i][j];
        }
    }
}

// ---------------- LSTM pointwise + output writes --------------------------
__global__ void lstm_kernel(const float* __restrict__ c0,
                            float* __restrict__ out, int out_size)
{
    int idx = blockIdx.x * 256 + threadIdx.x;
    if (idx >= B_ * RS) return;
    int b = idx / RS, j = idx % RS;
    const float* g = &g_gates[b * 4 * RS];
    float i_ = 1.f / (1.f + expf(-g[j]));
    float f_ = 1.f / (1.f + expf(-g[RS + j]));
    float gg = tanhf(g[2 * RS + j]);
    float o_ = 1.f / (1.f + expf(-g[3 * RS + j]));
    float c  = f_ * c0[idx] + i_ * gg;
    float h  = o_ * tanhf(c);
    out[idx] = h;
    if (out_size >= 3 * B_ * RS) {
        out[B_ * RS + idx]     = h;   // h_new[None]
        out[2 * B_ * RS + idx] = c;   // c_new[None]
    }
}

// ---------------- launch ---------------------------------------------------
extern "C" void kernel_launch(void* const* d_in, const int* in_sizes, int n_in,
                              void* d_out, int out_size)
{
    const float* xt        = (const float*)d_in[0];
    // d_in[1] = fc_feats (unused by reference)
    const float* att_feats = (const float*)d_in[2];
    const float* h0        = (const float*)d_in[3];
    const float* c0        = (const float*)d_in[4];
    const float* W_ctx     = (const float*)d_in[5];
    const float* b_ctx     = (const float*)d_in[6];
    const float* W_h2a     = (const float*)d_in[7];
    const float* b_h2a     = (const float*)d_in[8];
    const float* W_alpha   = (const float*)d_in[9];
    const float* b_alpha   = (const float*)d_in[10];
    const float* W_ih      = (const float*)d_in[11];
    const float* W_hh      = (const float*)d_in[12];
    float* out = (float*)d_out;

    cudaFuncSetAttribute(att_score_mma,
                         cudaFuncAttributeMaxDynamicSharedMemorySize,
                         STAGES * STG);

    cvtA_kernel<<<(int)(((size_t)BL * AF) / 1024), 256>>>(att_feats);
    cvtW_kernel<<<(AH * AF) / 1024, 256>>>(W_ctx);
    att_h_kernel<<<dim3(AH / 64, B_ / 64), 256>>>(h0, W_h2a, b_h2a, b_ctx);
    att_score_mma<<<dim3(AH / TN, BL / TM), 256, STAGES * STG>>>(W_alpha);
    softmax_attres_kernel<<<B_, 256>>>(b_alpha);
    gates_kernel<<<dim3(4 * RS / 64, B_ / 64), 256>>>(xt, h0, W_ih, W_hh);
    lstm_kernel<<<(B_ * RS + 255) / 256, 256>>>(c0, out, out_size);
}